// round 17
// baseline (speedup 1.0000x reference)
#include <cuda_runtime.h>
#include <stdint.h>

// Problem constants (fixed by the reference)
#define T_  4
#define N_  50000
#define D_  32
#define E_  800000
#define SLOT_ 64             // CSR slot stride (Poisson(16) max-degree ~47)

// Scratch (allocation-free rule: __device__ globals)
// g_cur starts zeroed (static init) and is re-zeroed by fused_kernel at the
// end of every launch, so no explicit zero pass is needed per invocation.
__device__ int   g_cur[N_];                  // CSR cursor == in-degree after build
__device__ float g_dinv[N_];                 // rsqrt(deg+1)
__device__ int   g_csr[(size_t)N_ * SLOT_];  // src indices per dst
__device__ int   g_is_i64;                   // edge_index dtype flag

// ---------------------------------------------------------------------------
__device__ __forceinline__ int load_idx(const void* ei, long long pos, int is64) {
    if (is64) return (int)((const long long*)ei)[pos];
    return ((const int*)ei)[pos];
}

// volatile .cg vector load: consecutive uses CANNOT be reordered/interleaved
// by the compiler -> forces all batch loads to issue back-to-back (max MLP).
__device__ __forceinline__ float4 ldcg4(const void* p) {
    float4 v;
    asm volatile("ld.global.cg.v4.f32 {%0,%1,%2,%3}, [%4];"
                 : "=f"(v.x), "=f"(v.y), "=f"(v.z), "=f"(v.w) : "l"(p));
    return v;
}

// ---------------------------------------------------------------------------
// Kd: dtype detect — one warp, ballot over 64 probes.
// int32 read as int64 packs two random indices -> >= N with overwhelming prob.
// ---------------------------------------------------------------------------
__global__ void detect_kernel(const void* ei) {
    const long long* p = (const long long*)ei;
    long long a = p[threadIdx.x];
    long long b = p[threadIdx.x + 32];
    bool good = (a >= 0 && a < N_ && b >= 0 && b < N_);
    unsigned m = __ballot_sync(0xffffffffu, good);
    if (threadIdx.x == 0) g_is_i64 = (m == 0xffffffffu) ? 1 : 0;
}

// ---------------------------------------------------------------------------
// K1: build CSR — cursor atomic doubles as the degree count.
// ---------------------------------------------------------------------------
__global__ void build_kernel(const void* __restrict__ ei) {
    int e = blockIdx.x * blockDim.x + threadIdx.x;
    if (e >= E_) return;
    int is64 = g_is_i64;
    int src = load_idx(ei, e, is64);
    int dst = load_idx(ei, (long long)E_ + e, is64);
    int pos = atomicAdd(&g_cur[dst], 1);
    if (pos < SLOT_) g_csr[(size_t)dst * SLOT_ + pos] = src;
}

// ---------------------------------------------------------------------------
// K1b: dinv
// ---------------------------------------------------------------------------
__global__ void dinv_kernel() {
    int n = blockIdx.x * blockDim.x + threadIdx.x;
    if (n >= N_) return;
    g_dinv[n] = rsqrtf((float)g_cur[n] + 1.0f);
}

// ---------------------------------------------------------------------------
// K2: fused aggregate(s) -> GEMM(W) -> IF scan.  agg(S·W) == agg(S)·W.
// One warp per node. Lane owns (t = lane>>3, float4 q = lane&7).
// Gather: unroll-8 with asm-volatile .cg loads (8 x 512B in flight/warp).
// Also re-zeros g_cur[n] for the next launch.
// ---------------------------------------------------------------------------
__global__ void __launch_bounds__(256)
fused_kernel(const float* __restrict__ s, const float* __restrict__ z,
             const float* __restrict__ W, float* __restrict__ out) {
    __shared__ float Wb[D_ * D_];          // 4KB
    __shared__ float buf[8][T_][36];       // padded: banks (4t+k)%32 distinct

    int tid = threadIdx.x;
    for (int i = tid; i < D_ * D_; i += 256) Wb[i] = W[i];
    __syncthreads();

    int w    = tid >> 5;
    int lane = tid & 31;
    int n    = blockIdx.x * 8 + w;
    if (n >= N_) return;

    int t = lane >> 3;            // 0..3
    int q = lane & 7;             // float4 index within the 128B row

    // per-lane base: row (t, node) lives at base + node*128 bytes
    const char* sbase = (const char*)(s + (size_t)t * N_ * D_ + 4 * q);
    #define SROW(i) ldcg4(sbase + ((unsigned)(i) << 7))

    float dinv_n = g_dinv[n];
    float sw = dinv_n * dinv_n;            // self-loop weight
    float4 acc = SROW(n);
    acc.x *= sw; acc.y *= sw; acc.z *= sw; acc.w *= sw;

    int deg = g_cur[n];
    if (lane == 0) g_cur[n] = 0;           // re-arm for the next launch
    if (deg > SLOT_) deg = SLOT_;
    const int* csr = &g_csr[(size_t)n * SLOT_];

    int j = 0;
    for (; j + 8 <= deg; j += 8) {
        int4 ca = *(const int4*)(csr + j);         // uniform LDG.128
        int4 cb = *(const int4*)(csr + j + 4);
        // 8 back-to-back volatile gathers: compiler cannot interleave
        float4 v0 = SROW(ca.x);
        float4 v1 = SROW(ca.y);
        float4 v2 = SROW(ca.z);
        float4 v3 = SROW(ca.w);
        float4 v4 = SROW(cb.x);
        float4 v5 = SROW(cb.y);
        float4 v6 = SROW(cb.z);
        float4 v7 = SROW(cb.w);
        float n0 = __ldg(&g_dinv[ca.x]) * dinv_n;
        float n1 = __ldg(&g_dinv[ca.y]) * dinv_n;
        float n2 = __ldg(&g_dinv[ca.z]) * dinv_n;
        float n3 = __ldg(&g_dinv[ca.w]) * dinv_n;
        float n4 = __ldg(&g_dinv[cb.x]) * dinv_n;
        float n5 = __ldg(&g_dinv[cb.y]) * dinv_n;
        float n6 = __ldg(&g_dinv[cb.z]) * dinv_n;
        float n7 = __ldg(&g_dinv[cb.w]) * dinv_n;
        acc.x = fmaf(v0.x, n0, acc.x);
        acc.y = fmaf(v0.y, n0, acc.y);
        acc.z = fmaf(v0.z, n0, acc.z);
        acc.w = fmaf(v0.w, n0, acc.w);
        acc.x = fmaf(v1.x, n1, acc.x);
        acc.y = fmaf(v1.y, n1, acc.y);
        acc.z = fmaf(v1.z, n1, acc.z);
        acc.w = fmaf(v1.w, n1, acc.w);
        acc.x = fmaf(v2.x, n2, acc.x);
        acc.y = fmaf(v2.y, n2, acc.y);
        acc.z = fmaf(v2.z, n2, acc.z);
        acc.w = fmaf(v2.w, n2, acc.w);
        acc.x = fmaf(v3.x, n3, acc.x);
        acc.y = fmaf(v3.y, n3, acc.y);
        acc.z = fmaf(v3.z, n3, acc.z);
        acc.w = fmaf(v3.w, n3, acc.w);
        acc.x = fmaf(v4.x, n4, acc.x);
        acc.y = fmaf(v4.y, n4, acc.y);
        acc.z = fmaf(v4.z, n4, acc.z);
        acc.w = fmaf(v4.w, n4, acc.w);
        acc.x = fmaf(v5.x, n5, acc.x);
        acc.y = fmaf(v5.y, n5, acc.y);
        acc.z = fmaf(v5.z, n5, acc.z);
        acc.w = fmaf(v5.w, n5, acc.w);
        acc.x = fmaf(v6.x, n6, acc.x);
        acc.y = fmaf(v6.y, n6, acc.y);
        acc.z = fmaf(v6.z, n6, acc.z);
        acc.w = fmaf(v6.w, n6, acc.w);
        acc.x = fmaf(v7.x, n7, acc.x);
        acc.y = fmaf(v7.y, n7, acc.y);
        acc.z = fmaf(v7.z, n7, acc.z);
        acc.w = fmaf(v7.w, n7, acc.w);
    }
    for (; j + 4 <= deg; j += 4) {
        int4 c = *(const int4*)(csr + j);
        float4 v0 = SROW(c.x);
        float4 v1 = SROW(c.y);
        float4 v2 = SROW(c.z);
        float4 v3 = SROW(c.w);
        float n0 = __ldg(&g_dinv[c.x]) * dinv_n;
        float n1 = __ldg(&g_dinv[c.y]) * dinv_n;
        float n2 = __ldg(&g_dinv[c.z]) * dinv_n;
        float n3 = __ldg(&g_dinv[c.w]) * dinv_n;
        acc.x = fmaf(v0.x, n0, acc.x);
        acc.y = fmaf(v0.y, n0, acc.y);
        acc.z = fmaf(v0.z, n0, acc.z);
        acc.w = fmaf(v0.w, n0, acc.w);
        acc.x = fmaf(v1.x, n1, acc.x);
        acc.y = fmaf(v1.y, n1, acc.y);
        acc.z = fmaf(v1.z, n1, acc.z);
        acc.w = fmaf(v1.w, n1, acc.w);
        acc.x = fmaf(v2.x, n2, acc.x);
        acc.y = fmaf(v2.y, n2, acc.y);
        acc.z = fmaf(v2.z, n2, acc.z);
        acc.w = fmaf(v2.w, n2, acc.w);
        acc.x = fmaf(v3.x, n3, acc.x);
        acc.y = fmaf(v3.y, n3, acc.y);
        acc.z = fmaf(v3.z, n3, acc.z);
        acc.w = fmaf(v3.w, n3, acc.w);
    }
    for (; j < deg; j++) {
        int i0 = __ldg(&csr[j]);
        float n0 = __ldg(&g_dinv[i0]) * dinv_n;
        float4 v0 = SROW(i0);
        acc.x = fmaf(v0.x, n0, acc.x);
        acc.y = fmaf(v0.y, n0, acc.y);
        acc.z = fmaf(v0.z, n0, acc.z);
        acc.w = fmaf(v0.w, n0, acc.w);
    }
    #undef SROW

    // stage aggregate in smem: buf[w][t][4q..4q+3]
    *(float4*)&buf[w][t][4 * q] = acc;
    __syncwarp();

    // x[t][4q..4q+3] = sum_k agg[t][k] * W[k][4q..4q+3]
    float4 x4 = make_float4(0.f, 0.f, 0.f, 0.f);
    #pragma unroll
    for (int k = 0; k < D_; k++) {
        float a = buf[w][t][k];                       // octet broadcast
        float4 wv = *(const float4*)&Wb[k * D_ + 4 * q];
        x4.x = fmaf(a, wv.x, x4.x);
        x4.y = fmaf(a, wv.y, x4.y);
        x4.z = fmaf(a, wv.z, x4.z);
        x4.w = fmaf(a, wv.w, x4.w);
    }
    __syncwarp();
    *(float4*)&buf[w][t][4 * q] = x4;                 // transpose staging
    __syncwarp();

    float x0 = buf[w][0][lane];
    float x1 = buf[w][1][lane];
    float x2 = buf[w][2][lane];
    float x3 = buf[w][3][lane];

    float y = 0.25f * (x0 + x1 + x2 + x3);

    size_t o_base = (size_t)n * D_ + lane;
    float v = 0.0f, o;
    v += x0; o = (v >= 1.0f) ? 1.0f : 0.0f; v -= o;
    __stcs(&out[0 * (size_t)N_ * D_ + o_base], o);
    v += x1; o = (v >= 1.0f) ? 1.0f : 0.0f; v -= o;
    __stcs(&out[1 * (size_t)N_ * D_ + o_base], o);
    v += x2; o = (v >= 1.0f) ? 1.0f : 0.0f; v -= o;
    __stcs(&out[2 * (size_t)N_ * D_ + o_base], o);
    v += x3; o = (v >= 1.0f) ? 1.0f : 0.0f; v -= o;
    __stcs(&out[3 * (size_t)N_ * D_ + o_base], o);

    __stcs(&out[4 * (size_t)N_ * D_ + o_base], z[o_base] + y);
}

// ---------------------------------------------------------------------------
extern "C" void kernel_launch(void* const* d_in, const int* in_sizes, int n_in,
                              void* d_out, int out_size) {
    const float* s  = (const float*)d_in[0];      // [T,N,D]
    const float* z  = (const float*)d_in[1];      // [N,D]
    const float* W  = (const float*)d_in[2];      // [D,D]
    const void*  ei = (const void*)d_in[3];       // [2,E] int32 or int64
    float* out = (float*)d_out;

    detect_kernel<<<1, 32>>>(ei);
    build_kernel<<<(E_ + 255) / 256, 256>>>(ei);
    dinv_kernel<<<(N_ + 255) / 256, 256>>>();
    fused_kernel<<<(N_ + 7) / 8, 256>>>(s, z, W, out);
}